// round 17
// baseline (speedup 1.0000x reference)
#include <cuda_runtime.h>
#include <math_constants.h>

#define B_      64
#define T_      2048
#define RNN_    1024
#define EMB_    512
#define ATT_    128
#define NF_     32
#define KS_     31
#define PAD_    15
#define TILE_   128
#define LPAD    132     // padded row stride for s_loc / s_wlT

// scratch (no allocs allowed)
__device__ float g_pq[B_ * ATT_];       // processed query [B,128]
__device__ float g_energy[B_ * T_];     // pre-softmax energies [B,T]
__device__ float g_prob[B_ * T_];       // normalized attention weights [B,T]

typedef unsigned long long u64;

__device__ __forceinline__ u64 pack2(float lo, float hi) {
    u64 r;
    asm("mov.b64 %0, {%1, %2};" : "=l"(r) : "f"(lo), "f"(hi));
    return r;
}
__device__ __forceinline__ void unpack2(u64 v, float& lo, float& hi) {
    asm("mov.b64 {%0, %1}, %2;" : "=f"(lo), "=f"(hi) : "l"(v));
}
__device__ __forceinline__ void fma2(u64& acc, u64 a, u64 b) {
    asm("fma.rn.f32x2 %0, %1, %2, %0;" : "+l"(acc) : "l"(a), "l"(b));
}
__device__ __forceinline__ void add2(u64& acc, u64 a) {
    asm("add.rn.f32x2 %0, %0, %1;" : "+l"(acc) : "l"(a));
}

// ---------------------------------------------------------------------------
// K1: g_pq[b,a] = sum_r query[b,r] * W_query[a,r]
// grid 512: block = (b, chunk of 16 a). 8 warps x 2 outputs per warp.
// ---------------------------------------------------------------------------
__global__ __launch_bounds__(256) void k_query(const float* __restrict__ q,
                                               const float* __restrict__ Wq) {
    const int b = blockIdx.x >> 3;
    const int ch = blockIdx.x & 7;
    const int tid = threadIdx.x;
    const int w = tid >> 5, lane = tid & 31;
    __shared__ float4 s_q[256];
    s_q[tid] = reinterpret_cast<const float4*>(q + (size_t)b * RNN_)[tid];
    __syncthreads();
    const int a0 = ch * 16 + w * 2;
    const float4* w0 = reinterpret_cast<const float4*>(Wq + (size_t)a0 * RNN_);
    const float4* w1 = w0 + 256;
    float acc0 = 0.f, acc1 = 0.f;
#pragma unroll
    for (int j = 0; j < 8; j++) {
        float4 x = s_q[j * 32 + lane];
        float4 u = w0[j * 32 + lane];
        float4 v = w1[j * 32 + lane];
        acc0 += u.x * x.x + u.y * x.y + u.z * x.z + u.w * x.w;
        acc1 += v.x * x.x + v.y * x.y + v.z * x.z + v.w * x.w;
    }
#pragma unroll
    for (int off = 16; off; off >>= 1) {
        acc0 += __shfl_xor_sync(0xffffffffu, acc0, off);
        acc1 += __shfl_xor_sync(0xffffffffu, acc1, off);
    }
    if (lane == 0) {
        g_pq[b * ATT_ + a0] = acc0;
        g_pq[b * ATT_ + a0 + 1] = acc1;
    }
}

// ---------------------------------------------------------------------------
// K2: energies as a register-tiled GEMM. grid (16, 64), 256 threads.
//   conv (split over 2 f-halves) -> s_loc[k][t]  (transposed, stride 132)
//   Wl staged transposed        -> s_wlT[k][a]   (stride 132)
//   GEMM: thread tile = 4t x 16a, acc = 32 x f32x2, init from pm via LDG.
//   epilogue: +pq (packed), tanh, v-dot, 8-wide smem reduce per t.
// ---------------------------------------------------------------------------
__global__ __launch_bounds__(256, 2) void k_energy(const float* __restrict__ pm,
                                                   const float* __restrict__ cat,
                                                   const int* __restrict__ mask,
                                                   const float* __restrict__ cw,
                                                   const float* __restrict__ Wl,
                                                   const float* __restrict__ vw) {
    const int b = blockIdx.y;
    const int t0g = blockIdx.x * TILE_;
    const int tid = threadIdx.x;

    __shared__ float s_cat[2][TILE_ + 32];                  // 1.3 KB
    __shared__ __align__(16) float s_cw[2][NF_][32];        // 8 KB
    __shared__ __align__(16) float s_loc[NF_ * LPAD];       // 16.9 KB [k][t]
    __shared__ __align__(16) float s_wlT[NF_ * LPAD];       // 16.9 KB [k][a]
    __shared__ float s_red2[TILE_ * 9];                     // 4.6 KB

    // ---- stage: conv window, conv weights, Wl transposed ----
#pragma unroll
    for (int c = 0; c < 2; c++) {
        for (int i = tid; i < TILE_ + 32; i += 256) {
            int g = t0g - PAD_ + i;
            float v = 0.f;
            if (i < TILE_ + 2 * PAD_ && g >= 0 && g < T_)
                v = cat[((size_t)(b * 2 + c)) * T_ + g];
            s_cat[c][i] = v;
        }
    }
    for (int i = tid; i < 2 * NF_ * 32; i += 256) {
        int c = i >> 10;
        int f = (i >> 5) & 31;
        int k = i & 31;
        s_cw[c][f][k] = (k < KS_) ? cw[(f * 2 + c) * KS_ + k] : 0.f;
    }
    // Wl[a][f] (coalesced read) -> s_wlT[f*LPAD + a]
    for (int i = tid; i < ATT_ * NF_; i += 256) {
        int a = i >> 5, f = i & 31;
        s_wlT[f * LPAD + a] = Wl[i];
    }
    __syncthreads();

    // ---- conv: 2 threads per t (one per 16-filter half) ----
    {
        const int t = tid & 127;
        const int half = tid >> 7;
        float loc[16];
#pragma unroll
        for (int i = 0; i < 16; i++) loc[i] = 0.f;
#pragma unroll
        for (int c = 0; c < 2; c++) {
            float xr[32];
#pragma unroll
            for (int i = 0; i < 32; i++) xr[i] = s_cat[c][t + i];
#pragma unroll
            for (int j = 0; j < 16; j++) {
                const int f = half * 16 + j;
                float a = 0.f;
#pragma unroll
                for (int kk = 0; kk < 8; kk++) {
                    float4 w = *reinterpret_cast<const float4*>(&s_cw[c][f][4 * kk]);
                    a += w.x * xr[4 * kk] + w.y * xr[4 * kk + 1] +
                         w.z * xr[4 * kk + 2] + w.w * xr[4 * kk + 3];
                }
                loc[j] += a;
            }
        }
#pragma unroll
        for (int j = 0; j < 16; j++)
            s_loc[(half * 16 + j) * LPAD + t] = loc[j];
    }

    // ---- thread tile: 4 t x 16 a ----
    const int ta = tid & 7;             // a-tile 0..7
    const int tts = tid >> 3;           // t-tile 0..31
    const int a0 = ta * 16;
    const int tt0 = tts * 4;

    // acc init = pm tile (global, coalesced; float4 == two f32x2 pairs)
    u64 acc[4][8];
#pragma unroll
    for (int r = 0; r < 4; r++) {
        const ulonglong2* pmr = reinterpret_cast<const ulonglong2*>(
            pm + ((size_t)(b * T_) + t0g + tt0 + r) * ATT_ + a0);
        ulonglong2 p0 = pmr[0], p1 = pmr[1], p2 = pmr[2], p3 = pmr[3];
        acc[r][0] = p0.x; acc[r][1] = p0.y;
        acc[r][2] = p1.x; acc[r][3] = p1.y;
        acc[r][4] = p2.x; acc[r][5] = p2.y;
        acc[r][6] = p3.x; acc[r][7] = p3.y;
    }
    __syncthreads();

    // ---- GEMM over k=32: 32 independent packed accumulator chains ----
#pragma unroll 8
    for (int k = 0; k < NF_; k++) {
        float4 lt = *reinterpret_cast<const float4*>(&s_loc[k * LPAD + tt0]);
        u64 l0 = pack2(lt.x, lt.x);
        u64 l1 = pack2(lt.y, lt.y);
        u64 l2 = pack2(lt.z, lt.z);
        u64 l3 = pack2(lt.w, lt.w);
        const ulonglong2* wr = reinterpret_cast<const ulonglong2*>(
            &s_wlT[k * LPAD + a0]);
        ulonglong2 w0 = wr[0], w1 = wr[1], w2 = wr[2], w3 = wr[3];
#define ROWFMA(r, l)                                                     \
        fma2(acc[r][0], l, w0.x); fma2(acc[r][1], l, w0.y);              \
        fma2(acc[r][2], l, w1.x); fma2(acc[r][3], l, w1.y);              \
        fma2(acc[r][4], l, w2.x); fma2(acc[r][5], l, w2.y);              \
        fma2(acc[r][6], l, w3.x); fma2(acc[r][7], l, w3.y);
        ROWFMA(0, l0) ROWFMA(1, l1) ROWFMA(2, l2) ROWFMA(3, l3)
#undef ROWFMA
    }

    // ---- epilogue: +pq, tanh, v-weighted reduce over this thread's 16 a ----
    u64 pqp[4 * 2];
    {
        const ulonglong2* pq2 = reinterpret_cast<const ulonglong2*>(
            g_pq + b * ATT_ + a0);
#pragma unroll
        for (int q = 0; q < 4; q++) {
            ulonglong2 v = pq2[q];
            pqp[2 * q] = v.x; pqp[2 * q + 1] = v.y;
        }
    }
    float4 vv[4];
    {
        const float4* v4 = reinterpret_cast<const float4*>(vw + a0);
#pragma unroll
        for (int q = 0; q < 4; q++) vv[q] = v4[q];
    }
#pragma unroll
    for (int r = 0; r < 4; r++) {
        float es = 0.f;
#pragma unroll
        for (int p = 0; p < 8; p++) {
            add2(acc[r][p], pqp[p]);
            float z0, z1;
            unpack2(acc[r][p], z0, z1);
            float th0, th1;
            asm("tanh.approx.f32 %0, %1;" : "=f"(th0) : "f"(z0));
            asm("tanh.approx.f32 %0, %1;" : "=f"(th1) : "f"(z1));
            float va0 = (p & 1) ? ((p >> 1) == 0 ? vv[0].z : (p >> 1) == 1 ? vv[1].z
                                  : (p >> 1) == 2 ? vv[2].z : vv[3].z)
                                : ((p >> 1) == 0 ? vv[0].x : (p >> 1) == 1 ? vv[1].x
                                  : (p >> 1) == 2 ? vv[2].x : vv[3].x);
            float va1 = (p & 1) ? ((p >> 1) == 0 ? vv[0].w : (p >> 1) == 1 ? vv[1].w
                                  : (p >> 1) == 2 ? vv[2].w : vv[3].w)
                                : ((p >> 1) == 0 ? vv[0].y : (p >> 1) == 1 ? vv[1].y
                                  : (p >> 1) == 2 ? vv[2].y : vv[3].y);
            es += va0 * th0 + va1 * th1;
        }
        s_red2[(tt0 + r) * 9 + ta] = es;
    }
    __syncthreads();
    if (tid < TILE_) {
        float e = 0.f;
#pragma unroll
        for (int i = 0; i < 8; i++) e += s_red2[tid * 9 + i];
        const int gt = b * T_ + t0g + tid;
        if (mask[gt] != 0) e = -CUDART_INF_F;
        g_energy[gt] = e;
    }
}

// ---------------------------------------------------------------------------
// K3a: softmax over T per b. 64 blocks x 256 threads; writes g_prob + the
// attention-weights output slice.
// ---------------------------------------------------------------------------
__global__ __launch_bounds__(256) void k_softmax(float* __restrict__ out) {
    const int b = blockIdx.x;
    const int tid = threadIdx.x;
    __shared__ float s_red[8];

    float4 e0 = reinterpret_cast<const float4*>(g_energy + b * T_)[tid * 2];
    float4 e1 = reinterpret_cast<const float4*>(g_energy + b * T_)[tid * 2 + 1];

    float lmax = fmaxf(fmaxf(fmaxf(e0.x, e0.y), fmaxf(e0.z, e0.w)),
                       fmaxf(fmaxf(e1.x, e1.y), fmaxf(e1.z, e1.w)));
#pragma unroll
    for (int off = 16; off; off >>= 1)
        lmax = fmaxf(lmax, __shfl_xor_sync(0xffffffffu, lmax, off));
    if ((tid & 31) == 0) s_red[tid >> 5] = lmax;
    __syncthreads();
    float bmax = s_red[0];
#pragma unroll
    for (int i = 1; i < 8; i++) bmax = fmaxf(bmax, s_red[i]);
    __syncthreads();

    float4 p0 = make_float4(__expf(e0.x - bmax), __expf(e0.y - bmax),
                            __expf(e0.z - bmax), __expf(e0.w - bmax));
    float4 p1 = make_float4(__expf(e1.x - bmax), __expf(e1.y - bmax),
                            __expf(e1.z - bmax), __expf(e1.w - bmax));
    float lsum = (p0.x + p0.y) + (p0.z + p0.w) + (p1.x + p1.y) + (p1.z + p1.w);
#pragma unroll
    for (int off = 16; off; off >>= 1)
        lsum += __shfl_xor_sync(0xffffffffu, lsum, off);
    if ((tid & 31) == 0) s_red[tid >> 5] = lsum;
    __syncthreads();
    float bsum = 0.f;
#pragma unroll
    for (int i = 0; i < 8; i++) bsum += s_red[i];
    const float inv = 1.f / bsum;

    p0.x *= inv; p0.y *= inv; p0.z *= inv; p0.w *= inv;
    p1.x *= inv; p1.y *= inv; p1.z *= inv; p1.w *= inv;
    reinterpret_cast<float4*>(g_prob + b * T_)[tid * 2] = p0;
    reinterpret_cast<float4*>(g_prob + b * T_)[tid * 2 + 1] = p1;
    float* ow = out + B_ * EMB_ + b * T_;
    reinterpret_cast<float4*>(ow)[tid * 2] = p0;
    reinterpret_cast<float4*>(ow)[tid * 2 + 1] = p1;
}

// ---------------------------------------------------------------------------
// K3b: context matvec (77-78% DRAM is this pattern's ceiling; finer grids
// verified not to help). grid (4, B), 512 threads = 8 t-phases x 64 d
// (float2), 8-deep load batching for DRAM MLP.
// ---------------------------------------------------------------------------
__global__ __launch_bounds__(512) void k_ctx(const float* __restrict__ mem,
                                             float* __restrict__ out) {
    const int b = blockIdx.y;
    const int dc = blockIdx.x;      // 0..3 -> 128 dims each
    const int tid = threadIdx.x;

    __shared__ float s_p[T_];
    __shared__ float2 s_acc[512];

    reinterpret_cast<float4*>(s_p)[tid] =
        reinterpret_cast<const float4*>(g_prob + b * T_)[tid];
    __syncthreads();

    const int ph = tid >> 6;        // 0..7
    const float2* mp = reinterpret_cast<const float2*>(
        mem + (size_t)b * T_ * EMB_ + dc * 128) + (tid & 63);
    float2 acc = make_float2(0.f, 0.f);
    for (int tb = ph; tb < T_; tb += 64) {
        float2 r[8];
#pragma unroll
        for (int u = 0; u < 8; u++) r[u] = mp[(size_t)(tb + u * 8) * 256];
#pragma unroll
        for (int u = 0; u < 8; u++) {
            float p = s_p[tb + u * 8];
            acc.x += p * r[u].x;
            acc.y += p * r[u].y;
        }
    }
    s_acc[tid] = acc;
    __syncthreads();
    if (tid < 64) {
        float2 tot = make_float2(0.f, 0.f);
#pragma unroll
        for (int k = 0; k < 8; k++) {
            float2 v = s_acc[k * 64 + tid];
            tot.x += v.x;
            tot.y += v.y;
        }
        reinterpret_cast<float2*>(out + b * EMB_ + dc * 128)[tid] = tot;
    }
}

// ---------------------------------------------------------------------------
extern "C" void kernel_launch(void* const* d_in, const int* in_sizes, int n_in,
                              void* d_out, int out_size) {
    const float* query = (const float*)d_in[0];
    const float* pm    = (const float*)d_in[1];
    const float* cat   = (const float*)d_in[2];
    const int*   mask  = (const int*)d_in[3];
    const float* mem   = (const float*)d_in[4];
    const float* Wq    = (const float*)d_in[5];
    const float* cw    = (const float*)d_in[6];
    const float* Wl    = (const float*)d_in[7];
    const float* vw    = (const float*)d_in[8];
    float* out = (float*)d_out;

    k_query<<<512, 256>>>(query, Wq);
    dim3 g2(T_ / TILE_, B_);
    k_energy<<<g2, 256>>>(pm, cat, mask, cw, Wl, vw);
    k_softmax<<<B_, 256>>>(out);
    dim3 g3(4, B_);
    k_ctx<<<g3, 512>>>(mem, out);
}